// round 9
// baseline (speedup 1.0000x reference)
#include <cuda_runtime.h>
#include <cuda_fp16.h>
#include <math.h>
#include <stdint.h>

#define BB 8
#define NN 4096
#define KK 16
#define CC 64
#define PP (BB*NN*KK)        // 524288 positions
#define C_IN 131
#define KC0 160              // padded input channels, order: [f2(64)|f1(64)|xyz(3)|0(29)]
#define BN_EPS 1e-3f

// dynamic smem layout (bytes): 3 X bufs + 3 W bufs (128 rows x 80B each) + scalars
#define XBUF(s) ((s)*10240)
#define WBUF(s) (30720 + (s)*10240)
#define SC_BIAS 61440
#define SC_SST  61952
#define SC_RED  62976
#define SMEM_BYTES 64000

// ---------------- scratch ----------------
__device__ int    g_idx[PP];
__device__ __align__(16) __half g_xh[(size_t)PP * KC0];      // 168MB packed gather rows
__device__ __align__(16) __half g_y0h[(size_t)64 * PP * 2];  // pair-interleaved [c2][pos][2]
__device__ __align__(16) __half g_y1h[(size_t)64 * PP * 2];
__device__ float  g_stats[6*128];
__device__ float  g_sst[6*128];
__device__ __align__(16) __half g_w0h[128*KC0];              // [n][k] permuted to new order
__device__ __align__(16) __half g_w1h[128*128];
__device__ __align__(16) __half g_w2h[128*128];
__device__ __align__(16) __half g_f2t[(size_t)BB*NN*64];     // [b][n][c] half
__device__ __align__(16) __half g_f1t[(size_t)BB*NN*64];
__device__ float4 g_p2t[BB*NN];
__device__ float4 g_p1t[BB*NN];

__device__ __forceinline__ uint32_t smem_u32(const void* p) {
    uint32_t a;
    asm("{ .reg .u64 t; cvta.to.shared.u64 t, %1; cvt.u32.u64 %0, t; }" : "=r"(a) : "l"(p));
    return a;
}
__device__ __forceinline__ void cp16(uint32_t dst, const void* src) {
    asm volatile("cp.async.ca.shared.global [%0], [%1], 16;" :: "r"(dst), "l"(src));
}
__device__ __forceinline__ void cp_commit() { asm volatile("cp.async.commit_group;"); }
template<int N> __device__ __forceinline__ void cp_wait() {
    asm volatile("cp.async.wait_group %0;" :: "n"(N) : "memory");
}
__device__ __forceinline__ void mma_f16(float& d0, float& d1, float& d2, float& d3,
                                        uint32_t a0, uint32_t a1, uint32_t a2, uint32_t a3,
                                        uint32_t b0, uint32_t b1) {
    asm volatile("mma.sync.aligned.m16n8k16.row.col.f32.f16.f16.f32 "
        "{%0,%1,%2,%3}, {%4,%5,%6,%7}, {%8,%9}, {%0,%1,%2,%3};"
        : "+f"(d0), "+f"(d1), "+f"(d2), "+f"(d3)
        : "r"(a0), "r"(a1), "r"(a2), "r"(a3), "r"(b0), "r"(b1));
}

// ---------------- prep: transposed source tables + packed half weights ----------------
__global__ void prep_kernel(const float* __restrict__ W0,
                            const float* __restrict__ W1,
                            const float* __restrict__ W2,
                            const float* __restrict__ p1,
                            const float* __restrict__ p2,
                            const float* __restrict__ f1,
                            const float* __restrict__ f2) {
    int tid = blockIdx.x*blockDim.x + threadIdx.x;
    int stride = gridDim.x*blockDim.x;
    for (int i = tid; i < BB*NN*64; i += stride) {
        int c = i & 63, n = (i >> 6) & (NN-1), b = i >> 18;
        g_f2t[i] = __float2half_rn(f2[((size_t)b*64 + c)*NN + n]);
        g_f1t[i] = __float2half_rn(f1[((size_t)b*64 + c)*NN + n]);
    }
    for (int i = tid; i < BB*NN; i += stride) {
        int n = i & (NN-1), b = i >> 12;
        g_p2t[i] = make_float4(p2[(b*3+0)*NN+n], p2[(b*3+1)*NN+n], p2[(b*3+2)*NN+n], 0.f);
        g_p1t[i] = make_float4(p1[(b*3+0)*NN+n], p1[(b*3+1)*NN+n], p1[(b*3+2)*NN+n], 0.f);
    }
    for (int i = tid; i < 128*KC0; i += stride) {
        int n = i / KC0, k = i % KC0;
        int src = (k < 64) ? 3 + k : (k < 128) ? 67 + (k - 64) : (k < 131) ? (k - 128) : -1;
        g_w0h[i] = (src >= 0) ? __float2half_rn(W0[n*C_IN + src]) : __float2half_rn(0.f);
    }
    for (int i = tid; i < 128*128; i += stride) {
        g_w1h[i] = __float2half_rn(W1[i]);
        g_w2h[i] = __float2half_rn(W2[i]);
    }
    for (int i = tid; i < 6*128; i += stride) g_stats[i] = 0.f;
}

// ---------------- KNN (top-16 via max-replacement) ----------------
__global__ void knn_kernel(const float* __restrict__ p1, const float* __restrict__ p2) {
    const int tid = threadIdx.x;
    const int b = blockIdx.x / (NN/128);
    const int n = (blockIdx.x % (NN/128)) * 128 + tid;

    const float qx = p1[(b*3+0)*NN + n];
    const float qy = p1[(b*3+1)*NN + n];
    const float qz = p1[(b*3+2)*NN + n];

    __shared__ float sx[1024], sy[1024], sz[1024];

    float dd[KK]; int ii[KK];
#pragma unroll
    for (int s = 0; s < KK; s++) { dd[s] = 3.4e38f; ii[s] = 0; }
    float worstd = 3.4e38f; int worsts = 0;

    for (int t0 = 0; t0 < NN; t0 += 1024) {
        __syncthreads();
        for (int i = tid; i < 1024; i += 128) {
            sx[i] = p2[(b*3+0)*NN + t0 + i];
            sy[i] = p2[(b*3+1)*NN + t0 + i];
            sz[i] = p2[(b*3+2)*NN + t0 + i];
        }
        __syncthreads();
        for (int j = 0; j < 1024; j++) {
            float dx = sx[j]-qx, dy = sy[j]-qy, dz = sz[j]-qz;
            float d = fmaf(dx, dx, fmaf(dy, dy, dz*dz));
            if (d < worstd) {
                int jg = t0 + j;
#pragma unroll
                for (int s = 0; s < KK; s++) if (s == worsts) { dd[s] = d; ii[s] = jg; }
                worstd = dd[0]; worsts = 0;
#pragma unroll
                for (int s = 1; s < KK; s++) if (dd[s] > worstd) { worstd = dd[s]; worsts = s; }
            }
        }
    }
#pragma unroll
    for (int s = 0; s < KK; s++) g_idx[(b*NN + n)*KK + s] = ii[s];
}

// ---------------- gather: build Xh[pos][160] half rows (vectorized, 4 lanes/position) ----------------
__global__ void gather_kernel() {
    int tid = threadIdx.x;
    int lid = tid & 31, wid = tid >> 5;
    int pos = blockIdx.x*64 + wid*8 + (lid >> 2);
    int sub = lid & 3;
    int j = g_idx[pos];
    int n = (pos >> 4) & (NN-1);
    int b = pos >> 16;
    const uint4* f2r = (const uint4*)(g_f2t + ((size_t)b*NN + j)*64);
    const uint4* f1r = (const uint4*)(g_f1t + ((size_t)b*NN + n)*64);
    uint4* dst = (uint4*)(g_xh + (size_t)pos*KC0);
    dst[sub]      = f2r[sub];
    dst[sub+4]    = f2r[sub+4];
    dst[8+sub]    = f1r[sub];
    dst[12+sub]   = f1r[sub+4];
    if (sub == 0) {
        float4 a = g_p2t[b*NN + j], c = g_p1t[b*NN + n];
        __half2 h01 = __floats2half2_rn(a.x - c.x, a.y - c.y);
        __half2 h23 = __floats2half2_rn(a.z - c.z, 0.f);
        uint4 v; v.x = *(uint32_t*)&h01; v.y = *(uint32_t*)&h23; v.z = 0u; v.w = 0u;
        dst[16] = v;
    } else {
        uint4 z = {0u,0u,0u,0u};
        dst[16 + sub] = z;
    }
}

// ---------------- fp16 HMMA GEMM, 256 thr, tile 128 pos x 128 ch, 2-deep cp.async ----------------
// MODE 0: X = packed Xh rows (pure cp.async, no transform, no swizzle)
// MODE 1: X = pair-interleaved half Y; BN+ReLU in reg path, swizzled STS
template<int KC, int MODE>
__global__ __launch_bounds__(256) void gemm_mma(
    const __half* __restrict__ Xp, const __half* __restrict__ Wk,
    const float* __restrict__ bias, const float* __restrict__ sst_in,
    __half* __restrict__ Yout, float* __restrict__ stats)
{
    extern __shared__ char sm[];
    float* s_bias = (float*)(sm + SC_BIAS);
    float* s_sst  = (float*)(sm + SC_SST);
    float* s_red  = (float*)(sm + SC_RED);

    const int tid = threadIdx.x;
    const int wid = tid >> 5;
    const int lid = tid & 31;
    const int g   = lid >> 2;
    const int tg  = lid & 3;
    const int pos0 = blockIdx.x * 128;

    const int warp_m = (wid & 1) * 64;
    const int warp_n = (wid >> 1) * 32;

    const int lp   = tid & 127;
    const int hsel = tid >> 7;       // 0/1
    const int kb2  = hsel * 8;       // MODE1 half2-word base
    const int swz  = (lp >> 3) & 3;

    if (tid < 128) s_bias[tid] = bias[tid];
    if (MODE == 1) s_sst[tid] = sst_in[tid];
    s_red[tid] = 0.f;
    __syncthreads();

    constexpr int NCH = KC / 32;
    const uint32_t smbase = smem_u32(sm);
    const uint32_t* Xw = (const uint32_t*)Xp;

    uint32_t xr32[8];

    // --- async issue helpers ---
    auto issueX = [&](int cc) {   // MODE 0 only
        uint32_t dstb = smbase + XBUF(cc % 3) + (uint32_t)lp*80 + hsel*32;
        const char* src = (const char*)Xp + (size_t)(pos0 + lp)*(KC*2) + cc*64 + hsel*32;
        cp16(dstb, src); cp16(dstb + 16, src + 16);
    };
    auto issueW = [&](int cc) {
        uint32_t wb = smbase + WBUF(cc % 3);
        const char* ws = (const char*)Wk + cc*64;
#pragma unroll
        for (int i = 0; i < 2; i++) {
            int q = tid + i*256;
            int n = q >> 2, jb = q & 3;
            cp16(wb + (uint32_t)(n*80 + jb*16), ws + (size_t)n*(KC*2) + jb*16);
        }
    };
    auto loadXr = [&](int cc) {   // MODE 1: 8 coalesced uint32 loads
        int cbase = cc*16 + kb2;
#pragma unroll
        for (int i = 0; i < 8; i++)
            xr32[i] = Xw[(size_t)(cbase + i)*PP + pos0 + lp];
    };
    auto storeXr = [&](int cc) {  // MODE 1: BN+ReLU + repack + swizzled STS
        uint32_t* Xb = (uint32_t*)(sm + XBUF(cc % 3));
        int cbase = cc*16 + kb2;
#pragma unroll
        for (int i = 0; i < 8; i++) {
            __half2 h = *(__half2*)&xr32[i];
            int ch = 2*(cbase + i);
            float f0 = __low2float(h), f1 = __high2float(h);
            f0 = fmaxf(fmaf(f0, s_sst[ch],   s_sst[128+ch]),   0.f);
            f1 = fmaxf(fmaf(f1, s_sst[ch+1], s_sst[128+ch+1]), 0.f);
            __half2 o = __floats2half2_rn(f0, f1);
            Xb[lp*20 + ((kb2 + i) ^ swz)] = *(uint32_t*)&o;
        }
    };

    // prologue: chunks 0,1 in flight
    if (MODE == 0) issueX(0);
    issueW(0); cp_commit();
    if (NCH > 1) { if (MODE == 0) issueX(1); issueW(1); cp_commit(); }
    if (MODE == 1) loadXr(0);

    float acc[4][4][4];
#pragma unroll
    for (int mt = 0; mt < 4; mt++)
#pragma unroll
        for (int nt = 0; nt < 4; nt++)
#pragma unroll
            for (int e = 0; e < 4; e++) acc[mt][nt][e] = 0.f;

#pragma unroll 1
    for (int ch = 0; ch < NCH; ch++) {
        if (MODE == 1) {
            storeXr(ch);                       // buf ch%3: readers (ch-3) long done
            if (ch + 1 < NCH) loadXr(ch + 1);  // global-only, issue before barrier
        }
        if (ch == NCH - 1) cp_wait<0>(); else cp_wait<1>();
        __syncthreads();
        if (ch + 2 < NCH) {                    // buf (ch+2)%3 = (ch-1)%3: drained by this barrier
            if (MODE == 0) issueX(ch + 2);
            issueW(ch + 2);
            cp_commit();
        }

        const uint32_t* Xr = (const uint32_t*)(sm + XBUF(ch % 3));
        const uint32_t* Wr = (const uint32_t*)(sm + WBUF(ch % 3));
#pragma unroll
        for (int ks = 0; ks < 2; ks++) {
            uint32_t a[4][4], bb[4][2];
#pragma unroll
            for (int mt = 0; mt < 4; mt++) {
                int row0 = warp_m + mt*16 + g, row1 = row0 + 8;
                int c0 = (MODE == 1) ? ((2*mt) & 3) : 0;
                int c1 = (MODE == 1) ? ((2*mt + 1) & 3) : 0;
                int j0 = 8*ks + (tg ^ c0), j1 = 8*ks + (tg ^ c1);
                a[mt][0] = Xr[row0*20 + j0];
                a[mt][1] = Xr[row1*20 + j1];
                a[mt][2] = Xr[row0*20 + j0 + 4];
                a[mt][3] = Xr[row1*20 + j1 + 4];
            }
#pragma unroll
            for (int nt = 0; nt < 4; nt++) {
                int n = warp_n + nt*8 + g;
                bb[nt][0] = Wr[n*20 + 8*ks + tg];
                bb[nt][1] = Wr[n*20 + 8*ks + tg + 4];
            }
#pragma unroll
            for (int mt = 0; mt < 4; mt++)
#pragma unroll
                for (int nt = 0; nt < 4; nt++)
                    mma_f16(acc[mt][nt][0], acc[mt][nt][1], acc[mt][nt][2], acc[mt][nt][3],
                            a[mt][0], a[mt][1], a[mt][2], a[mt][3],
                            bb[nt][0], bb[nt][1]);
        }
    }

    // ---------- epilogue: bias, direct pair-interleaved half stores, BN stats ----------
    uint32_t* Yw = (uint32_t*)Yout;
    float sp[4][2], qp[4][2];
#pragma unroll
    for (int nt = 0; nt < 4; nt++)
#pragma unroll
        for (int e = 0; e < 2; e++) { sp[nt][e] = 0.f; qp[nt][e] = 0.f; }

#pragma unroll
    for (int nt = 0; nt < 4; nt++) {
        int ch0 = warp_n + nt*8 + tg*2;
        int c2 = ch0 >> 1;
        float bv0 = s_bias[ch0], bv1 = s_bias[ch0+1];
        uint32_t* yrow = Yw + (size_t)c2*PP + pos0;
#pragma unroll
        for (int mt = 0; mt < 4; mt++) {
            int m = warp_m + mt*16 + g;
            float v0 = acc[mt][nt][0] + bv0;
            float v1 = acc[mt][nt][1] + bv1;
            float v2 = acc[mt][nt][2] + bv0;
            float v3 = acc[mt][nt][3] + bv1;
            __half2 ha = __floats2half2_rn(v0, v1);
            __half2 hb = __floats2half2_rn(v2, v3);
            yrow[m]     = *(uint32_t*)&ha;
            yrow[m + 8] = *(uint32_t*)&hb;
            sp[nt][0] += v0 + v2;  qp[nt][0] += fmaf(v0, v0, v2*v2);
            sp[nt][1] += v1 + v3;  qp[nt][1] += fmaf(v1, v1, v3*v3);
        }
    }
#pragma unroll
    for (int off = 4; off <= 16; off <<= 1) {
#pragma unroll
        for (int nt = 0; nt < 4; nt++)
#pragma unroll
            for (int e = 0; e < 2; e++) {
                sp[nt][e] += __shfl_xor_sync(0xffffffffu, sp[nt][e], off);
                qp[nt][e] += __shfl_xor_sync(0xffffffffu, qp[nt][e], off);
            }
    }
    if (g == 0) {
#pragma unroll
        for (int nt = 0; nt < 4; nt++)
#pragma unroll
            for (int e = 0; e < 2; e++) {
                int chn = warp_n + nt*8 + tg*2 + e;
                atomicAdd(&s_red[chn], sp[nt][e]);
                atomicAdd(&s_red[128 + chn], qp[nt][e]);
            }
    }
    __syncthreads();
    atomicAdd(&stats[tid], s_red[tid]);
}

// ---------------- BN finalize ----------------
__global__ void finalize_kernel(const float* __restrict__ stats,
                                const float* __restrict__ gamma,
                                const float* __restrict__ beta,
                                float* __restrict__ sst) {
    int chn = threadIdx.x;
    const float inv = 1.0f / (float)PP;
    float mean = stats[chn] * inv;
    float var  = stats[128 + chn] * inv - mean*mean;
    float s = gamma[chn] * rsqrtf(var + BN_EPS);
    sst[chn]       = s;
    sst[128 + chn] = fmaf(-mean, s, beta[chn]);
}

// ---------------- max over K + final BN+ReLU (pair layout) ----------------
__global__ void maxout_kernel(const __half* __restrict__ Yh, const float* __restrict__ sst,
                              float* __restrict__ out) {
    int gid = blockIdx.x*256 + threadIdx.x;   // B*64*NN pair-threads
    int n  = gid & (NN - 1);
    int c2 = (gid >> 12) & 63;
    int b  = gid >> 18;
    const uint4* src = (const uint4*)((const uint32_t*)Yh + (size_t)c2*PP + (size_t)(b*NN + n)*KK);
    __half2 m = __floats2half2_rn(-3.0e4f, -3.0e4f);
#pragma unroll
    for (int q = 0; q < 4; q++) {
        uint4 v = src[q];
        m = __hmax2(m, *(__half2*)&v.x);
        m = __hmax2(m, *(__half2*)&v.y);
        m = __hmax2(m, *(__half2*)&v.z);
        m = __hmax2(m, *(__half2*)&v.w);
    }
    float m0 = __low2float(m), m1 = __high2float(m);
    int o = 2*c2;
    out[((size_t)b*128 + o)*NN + n]     = fmaxf(fmaf(m0, sst[o],   sst[128+o]),   0.f);
    out[((size_t)b*128 + o + 1)*NN + n] = fmaxf(fmaf(m1, sst[o+1], sst[128+o+1]), 0.f);
}

// ---------------- launch ----------------
extern "C" void kernel_launch(void* const* d_in, const int* in_sizes, int n_in,
                              void* d_out, int out_size) {
    const float* p1  = (const float*)d_in[0];
    const float* p2  = (const float*)d_in[1];
    const float* f1  = (const float*)d_in[2];
    const float* f2  = (const float*)d_in[3];
    const float* W0  = (const float*)d_in[4];
    const float* b0  = (const float*)d_in[5];
    const float* g0  = (const float*)d_in[6];
    const float* be0 = (const float*)d_in[7];
    const float* W1  = (const float*)d_in[8];
    const float* b1  = (const float*)d_in[9];
    const float* g1  = (const float*)d_in[10];
    const float* be1 = (const float*)d_in[11];
    const float* W2  = (const float*)d_in[12];
    const float* b2  = (const float*)d_in[13];
    const float* g2  = (const float*)d_in[14];
    const float* be2 = (const float*)d_in[15];
    float* out = (float*)d_out;

    static float *stats = nullptr, *sst;
    static __half *xh, *y0h, *y1h, *w0h, *w1h, *w2h;
    if (!stats) {
        cudaGetSymbolAddress((void**)&stats, g_stats);
        cudaGetSymbolAddress((void**)&sst,   g_sst);
        cudaGetSymbolAddress((void**)&xh,    g_xh);
        cudaGetSymbolAddress((void**)&y0h,   g_y0h);
        cudaGetSymbolAddress((void**)&y1h,   g_y1h);
        cudaGetSymbolAddress((void**)&w0h,   g_w0h);
        cudaGetSymbolAddress((void**)&w1h,   g_w1h);
        cudaGetSymbolAddress((void**)&w2h,   g_w2h);
        cudaFuncSetAttribute(gemm_mma<KC0,0>, cudaFuncAttributeMaxDynamicSharedMemorySize, SMEM_BYTES);
        cudaFuncSetAttribute(gemm_mma<128,1>, cudaFuncAttributeMaxDynamicSharedMemorySize, SMEM_BYTES);
    }

    prep_kernel<<<1024, 256>>>(W0, W1, W2, p1, p2, f1, f2);          // launch 0
    knn_kernel<<<BB*(NN/128), 128>>>(p1, p2);                        // launch 1
    gather_kernel<<<PP/64, 256>>>();                                 // launch 2

    // launch 3 (ncu-profiled): gemm0, pure streaming cp.async
    gemm_mma<KC0, 0><<<PP/128, 256, SMEM_BYTES>>>(xh, w0h, b0, nullptr, y0h, stats + 0*256);
    finalize_kernel<<<1, 128>>>(stats + 0*256, g0, be0, sst + 0*256);

    gemm_mma<128, 1><<<PP/128, 256, SMEM_BYTES>>>(y0h, w1h, b1, sst + 0*256, y1h, stats + 1*256);
    finalize_kernel<<<1, 128>>>(stats + 1*256, g1, be1, sst + 1*256);

    gemm_mma<128, 1><<<PP/128, 256, SMEM_BYTES>>>(y1h, w2h, b2, sst + 1*256, y0h, stats + 2*256);
    finalize_kernel<<<1, 128>>>(stats + 2*256, g2, be2, sst + 2*256);

    maxout_kernel<<<(BB*64*NN)/256, 256>>>(y0h, sst + 2*256, out);
}